// round 11
// baseline (speedup 1.0000x reference)
#include <cuda_runtime.h>
#include <cuda_bf16.h>

// out[n,:] = x[n,:] * min(1, 1/||x[n,:]||) + noise[n,:]   (L2_NORM_CLIP = 1)
// N = 524288 rows, D = 128 fp32.
// One warp per row: lane i handles float4 chunk i (16B), so each warp touches
// exactly 512 contiguous bytes per tensor -> perfectly coalesced LDG.128/STG.128.

__global__ __launch_bounds__(256) void dp_clip_noise_kernel(
    const float4* __restrict__ x,
    const float4* __restrict__ noise,
    float4* __restrict__ out,
    int nrows)
{
    const int gwarp = (int)((blockIdx.x * blockDim.x + threadIdx.x) >> 5);
    const int lane  = threadIdx.x & 31;
    if (gwarp >= nrows) return;

    // Row `gwarp`, chunk `lane`: D=128 floats = 32 float4 per row.
    const long long idx = (long long)gwarp * 32 + lane;

    // Batch both loads up front (MLP=2 per thread) so DRAM latency overlaps.
    const float4 xv = x[idx];
    const float4 nv = noise[idx];

    // Per-lane partial sum of squares.
    float ssq = xv.x * xv.x + xv.y * xv.y + xv.z * xv.z + xv.w * xv.w;

    // Warp butterfly reduction across 32 lanes -> full-row ||x||^2 in every lane.
    #pragma unroll
    for (int off = 16; off > 0; off >>= 1)
        ssq += __shfl_xor_sync(0xFFFFFFFFu, ssq, off);

    // scale = 1 / max(norm, 1) = min(1, rsqrt(ssq)).  ssq==0 -> rsqrt=+inf -> 1.
    const float scale = fminf(1.0f, rsqrtf(ssq));

    float4 ov;
    ov.x = fmaf(xv.x, scale, nv.x);
    ov.y = fmaf(xv.y, scale, nv.y);
    ov.z = fmaf(xv.z, scale, nv.z);
    ov.w = fmaf(xv.w, scale, nv.w);
    out[idx] = ov;
}

extern "C" void kernel_launch(void* const* d_in, const int* in_sizes, int n_in,
                              void* d_out, int out_size)
{
    const float4* x     = (const float4*)d_in[0];
    const float4* noise = (const float4*)d_in[1];
    float4* out         = (float4*)d_out;

    const int D = 128;
    const int nrows = in_sizes[0] / D;          // 524288

    // One warp per row, 8 warps per 256-thread CTA.
    const int threads = 256;
    const int warps_per_block = threads / 32;
    const int blocks = (nrows + warps_per_block - 1) / warps_per_block;  // 65536

    dp_clip_noise_kernel<<<blocks, threads>>>(x, noise, out, nrows);
}

// round 12
// speedup vs baseline: 1.0025x; 1.0025x over previous
#include <cuda_runtime.h>
#include <cuda_bf16.h>

// out[n,:] = x[n,:] * min(1, 1/||x[n,:]||) + noise[n,:]   (L2_NORM_CLIP = 1)
// N = 524288 rows, D = 128 fp32.
//
// One warp per row-slot, grid-stride over 4 rows per warp with a 1-deep
// software pipeline: the NEXT row's x/noise loads are issued before the
// current row's shfl reduction + store, keeping 2 LDG.128 per thread in
// flight continuously (no dead window during the ~150-cycle reduction chain).
// All traffic is zero-reuse, so use .cs (evict-first streaming) on both
// loads and the store.

__global__ __launch_bounds__(256) void dp_clip_noise_kernel(
    const float4* __restrict__ x,
    const float4* __restrict__ noise,
    float4* __restrict__ out,
    int nrows)
{
    const int lane   = threadIdx.x & 31;
    const int warp   = (int)((blockIdx.x * blockDim.x + threadIdx.x) >> 5);
    const int nwarps = (int)((gridDim.x * blockDim.x) >> 5);

    int row = warp;
    if (row >= nrows) return;

    long long idx = (long long)row * 32 + lane;
    float4 xv = __ldcs(x + idx);
    float4 nv = __ldcs(noise + idx);

    while (true) {
        // ---- prefetch next row (issued before the reduction chain) ----
        const int next = row + nwarps;
        const bool more = next < nrows;
        float4 xn, nn;
        long long nidx = 0;
        if (more) {
            nidx = (long long)next * 32 + lane;
            xn = __ldcs(x + nidx);
            nn = __ldcs(noise + nidx);
        }

        // ---- process current row ----
        float ssq = xv.x * xv.x + xv.y * xv.y + xv.z * xv.z + xv.w * xv.w;
        #pragma unroll
        for (int off = 16; off > 0; off >>= 1)
            ssq += __shfl_xor_sync(0xFFFFFFFFu, ssq, off);

        // scale = 1/max(norm,1) = min(1, rsqrt(ssq)); ssq==0 -> inf -> 1.
        const float scale = fminf(1.0f, rsqrtf(ssq));

        float4 ov;
        ov.x = fmaf(xv.x, scale, nv.x);
        ov.y = fmaf(xv.y, scale, nv.y);
        ov.z = fmaf(xv.z, scale, nv.z);
        ov.w = fmaf(xv.w, scale, nv.w);
        __stcs(out + idx, ov);

        if (!more) break;
        row = next;
        idx = nidx;
        xv  = xn;
        nv  = nn;
    }
}

extern "C" void kernel_launch(void* const* d_in, const int* in_sizes, int n_in,
                              void* d_out, int out_size)
{
    const float4* x     = (const float4*)d_in[0];
    const float4* noise = (const float4*)d_in[1];
    float4* out         = (float4*)d_out;

    const int D = 128;
    const int nrows = in_sizes[0] / D;          // 524288

    // 8 warps per CTA, 4 rows per warp -> 16384 CTAs (vs 65536 before):
    // fewer wave transitions, and the pipeline keeps loads in flight.
    const int threads = 256;
    const int rows_per_warp = 4;
    const int warps_per_block = threads / 32;
    int blocks = (nrows + warps_per_block * rows_per_warp - 1)
               / (warps_per_block * rows_per_warp);
    if (blocks < 1) blocks = 1;

    dp_clip_noise_kernel<<<blocks, threads>>>(x, noise, out, nrows);
}